// round 1
// baseline (speedup 1.0000x reference)
#include <cuda_runtime.h>

// DynamicMaskHead: per-instance 3-layer MLP over all pixels.
// inputs (metadata order):
//   d_in[0] mask_feats        float32 (2, 8, 136, 200)
//   d_in[1] mask_head_params  float32 (128, 169)
//   d_in[2] instance_locations float32 (128, 2)   [x, y]
//   d_in[3] soi_table         float32 (5,)
//   d_in[4] im_inds           int32   (128,)
//   d_in[5] fpn_levels        int32   (128,)
//   d_in[6] mask_feat_stride  scalar (== 8, hardcoded; shapes are fixed)
// output: float32 (128, 1, 136, 200)

#define H_     136
#define W_     200
#define HW_    (H_ * W_)          // 27200
#define CH_    8
#define INCH_  8
#define NINST_ 128
#define NP_    169
#define STRIDE_ 8

#define PPT   4                   // pixels per thread
#define BLK   256                 // threads per block
#define TILE  (BLK * PPT)         // 1024 pixels per block

// param layout within the 169 floats:
//   w0 [0,80)    (8 x 10)
//   w1 [80,144)  (8 x 8)
//   w2 [144,152) (1 x 8)
//   b0 [152,160)
//   b1 [160,168)
//   b2 [168]

__global__ __launch_bounds__(BLK)
void dynamic_mask_head_kernel(
    const float* __restrict__ feats,     // (2, 8, HW)
    const float* __restrict__ params,    // (128, 169)
    const float* __restrict__ locs,      // (128, 2)
    const float* __restrict__ soi,       // (5,)
    const int*   __restrict__ im_inds,   // (128,)
    const int*   __restrict__ fpn,       // (128,)
    float*       __restrict__ out)       // (128, HW)
{
    __shared__ float sp[NP_];
    __shared__ float smeta[3];
    __shared__ int   simg;

    const int inst = blockIdx.y;
    const int tid  = threadIdx.x;

    // stage this instance's params into shared
    if (tid < NP_) sp[tid] = params[inst * NP_ + tid];
    if (tid == 0) {
        smeta[0] = locs[2 * inst + 0];
        smeta[1] = locs[2 * inst + 1];
        smeta[2] = 1.0f / soi[fpn[inst]];
        simg     = im_inds[inst];
    }
    __syncthreads();

    const float locx = smeta[0];
    const float locy = smeta[1];
    const float inv  = smeta[2];
    const float* __restrict__ fbase = feats + (size_t)simg * (INCH_ * HW_);

    const int base = blockIdx.x * TILE + tid;

    // ---- gather inputs: 2 rel coords + 8 feature channels per pixel ----
    float x[PPT][INCH_ + 2];
    int   pix[PPT];
    #pragma unroll
    for (int p = 0; p < PPT; p++) {
        const int pp = base + p * BLK;
        pix[p] = pp;
        const int cp  = (pp < HW_) ? pp : 0;
        const int row = cp / W_;
        const int col = cp - row * W_;
        const float fx = (float)(col * STRIDE_ + STRIDE_ / 2);
        const float fy = (float)(row * STRIDE_ + STRIDE_ / 2);
        x[p][0] = (locx - fx) * inv;
        x[p][1] = (locy - fy) * inv;
        #pragma unroll
        for (int c = 0; c < INCH_; c++)
            x[p][2 + c] = fbase[c * HW_ + cp];
    }

    // ---- layer 0: (8 x 10) + relu ----
    float h0[PPT][CH_];
    #pragma unroll
    for (int o = 0; o < CH_; o++) {
        float acc[PPT];
        const float b = sp[152 + o];
        #pragma unroll
        for (int p = 0; p < PPT; p++) acc[p] = b;
        #pragma unroll
        for (int i = 0; i < INCH_ + 2; i++) {
            const float w = sp[o * (INCH_ + 2) + i];
            #pragma unroll
            for (int p = 0; p < PPT; p++) acc[p] = fmaf(w, x[p][i], acc[p]);
        }
        #pragma unroll
        for (int p = 0; p < PPT; p++) h0[p][o] = fmaxf(acc[p], 0.0f);
    }

    // ---- layer 1: (8 x 8) + relu ----
    float h1[PPT][CH_];
    #pragma unroll
    for (int o = 0; o < CH_; o++) {
        float acc[PPT];
        const float b = sp[160 + o];
        #pragma unroll
        for (int p = 0; p < PPT; p++) acc[p] = b;
        #pragma unroll
        for (int i = 0; i < CH_; i++) {
            const float w = sp[80 + o * CH_ + i];
            #pragma unroll
            for (int p = 0; p < PPT; p++) acc[p] = fmaf(w, h0[p][i], acc[p]);
        }
        #pragma unroll
        for (int p = 0; p < PPT; p++) h1[p][o] = fmaxf(acc[p], 0.0f);
    }

    // ---- layer 2: (1 x 8), no relu ----
    float res[PPT];
    const float b2 = sp[168];
    #pragma unroll
    for (int p = 0; p < PPT; p++) res[p] = b2;
    #pragma unroll
    for (int i = 0; i < CH_; i++) {
        const float w = sp[144 + i];
        #pragma unroll
        for (int p = 0; p < PPT; p++) res[p] = fmaf(w, h1[p][i], res[p]);
    }

    // ---- store ----
    float* __restrict__ obase = out + (size_t)inst * HW_;
    #pragma unroll
    for (int p = 0; p < PPT; p++)
        if (pix[p] < HW_) obase[pix[p]] = res[p];
}

extern "C" void kernel_launch(void* const* d_in, const int* in_sizes, int n_in,
                              void* d_out, int out_size)
{
    const float* feats   = (const float*)d_in[0];
    const float* params  = (const float*)d_in[1];
    const float* locs    = (const float*)d_in[2];
    const float* soi     = (const float*)d_in[3];
    const int*   im_inds = (const int*)  d_in[4];
    const int*   fpn     = (const int*)  d_in[5];
    float*       out     = (float*)      d_out;

    dim3 grid((HW_ + TILE - 1) / TILE, NINST_);
    dynamic_mask_head_kernel<<<grid, BLK>>>(feats, params, locs, soi,
                                            im_inds, fpn, out);
}

// round 2
// speedup vs baseline: 1.1232x; 1.1232x over previous
#include <cuda_runtime.h>

// DynamicMaskHead: per-instance 3-layer 1x1-conv MLP (10->8->8->1) over 27200 pixels.
// Packed f32x2 FMA version: each thread handles 4 consecutive pixels = 2 f32x2 lanes.

#define H_      136
#define W_      200
#define HW_     27200
#define CH_     8
#define INCH_   8
#define NINST_  128
#define NP_     169
#define STRIDE_ 8

#define BLK   256
#define NQ    (HW_ / 4)           // 6800 float4 groups per image plane
#define QPB   BLK                 // one float4 group per thread
#define GRIDX ((NQ + QPB - 1) / QPB)   // 27

typedef unsigned long long u64;

__device__ __forceinline__ u64 pack2(float lo, float hi) {
    u64 r; asm("mov.b64 %0, {%1, %2};" : "=l"(r) : "f"(lo), "f"(hi)); return r;
}
__device__ __forceinline__ void unpack2(u64 v, float& lo, float& hi) {
    asm("mov.b64 {%0, %1}, %2;" : "=f"(lo), "=f"(hi) : "l"(v));
}
__device__ __forceinline__ u64 ffma2(u64 a, u64 b, u64 c) {
    u64 d; asm("fma.rn.f32x2 %0, %1, %2, %3;" : "=l"(d) : "l"(a), "l"(b), "l"(c)); return d;
}
__device__ __forceinline__ u64 relu2(u64 v) {
    float lo, hi; unpack2(v, lo, hi);
    lo = fmaxf(lo, 0.0f); hi = fmaxf(hi, 0.0f);
    return pack2(lo, hi);
}

// param layout: w0 [0,80) (8x10) | w1 [80,144) (8x8) | w2 [144,152) (1x8)
//               b0 [152,160) | b1 [160,168) | b2 [168]

__global__ __launch_bounds__(BLK)
void dmh_kernel(const float* __restrict__ feats,   // (2, 8, HW)
                const float* __restrict__ params,  // (128, 169)
                const float* __restrict__ locs,    // (128, 2)
                const float* __restrict__ soi,     // (5,)
                const int*   __restrict__ im_inds, // (128,)
                const int*   __restrict__ fpn,     // (128,)
                float*       __restrict__ out)     // (128, HW)
{
    __shared__ u64   sp[NP_];     // each weight duplicated into both f32x2 lanes
    __shared__ float smeta[3];
    __shared__ int   simg;

    const int inst = blockIdx.y;
    const int tid  = threadIdx.x;

    if (tid < NP_) {
        float w = params[inst * NP_ + tid];
        sp[tid] = pack2(w, w);
    }
    if (tid == 0) {
        smeta[0] = locs[2 * inst + 0];
        smeta[1] = locs[2 * inst + 1];
        smeta[2] = 1.0f / soi[fpn[inst]];
        simg     = im_inds[inst];
    }
    __syncthreads();

    const float locx = smeta[0];
    const float locy = smeta[1];
    const float inv  = smeta[2];
    const float* __restrict__ fbase = feats + (size_t)simg * (INCH_ * HW_);

    const int q     = blockIdx.x * QPB + tid;   // float4 group index
    const bool live = (q < NQ);
    const int qc    = live ? q : 0;
    const int p0    = qc * 4;                   // first pixel; W divisible by 4 -> same row

    // pixel coordinates (all 4 pixels share a row)
    const int row  = qc / 50;                   // 50 float4 groups per row
    const int col0 = (qc - row * 50) * 4;
    const float fy  = (float)(row * STRIDE_ + STRIDE_ / 2);
    const float fx0 = (float)(col0 * STRIDE_ + STRIDE_ / 2);

    // ---- layer 0: 10 -> 8, incremental accumulation, packed pairs ----
    u64 a0[2][CH_];
    #pragma unroll
    for (int o = 0; o < CH_; o++) {
        const u64 b = sp[152 + o];
        a0[0][o] = b; a0[1][o] = b;
    }

    {   // input 0: rel-x  (4 distinct values)
        const float rx0 = (locx - fx0) * inv;
        const float rx1 = (locx - (fx0 + 8.0f)) * inv;
        const float rx2 = (locx - (fx0 + 16.0f)) * inv;
        const float rx3 = (locx - (fx0 + 24.0f)) * inv;
        const u64 x0 = pack2(rx0, rx1);
        const u64 x1 = pack2(rx2, rx3);
        #pragma unroll
        for (int o = 0; o < CH_; o++) {
            const u64 w = sp[o * 10 + 0];
            a0[0][o] = ffma2(w, x0, a0[0][o]);
            a0[1][o] = ffma2(w, x1, a0[1][o]);
        }
    }
    {   // input 1: rel-y (same for all 4 pixels)
        const float ry = (locy - fy) * inv;
        const u64 xy = pack2(ry, ry);
        #pragma unroll
        for (int o = 0; o < CH_; o++) {
            const u64 w = sp[o * 10 + 1];
            a0[0][o] = ffma2(w, xy, a0[0][o]);
            a0[1][o] = ffma2(w, xy, a0[1][o]);
        }
    }
    #pragma unroll
    for (int c = 0; c < INCH_; c++) {   // inputs 2..9: feature channels, LDG.128 each
        const float4 f = *reinterpret_cast<const float4*>(fbase + (size_t)c * HW_ + p0);
        const u64 x0 = pack2(f.x, f.y);
        const u64 x1 = pack2(f.z, f.w);
        #pragma unroll
        for (int o = 0; o < CH_; o++) {
            const u64 w = sp[o * 10 + 2 + c];
            a0[0][o] = ffma2(w, x0, a0[0][o]);
            a0[1][o] = ffma2(w, x1, a0[1][o]);
        }
    }
    u64 h0[2][CH_];
    #pragma unroll
    for (int o = 0; o < CH_; o++) {
        h0[0][o] = relu2(a0[0][o]);
        h0[1][o] = relu2(a0[1][o]);
    }

    // ---- layer 1: 8 -> 8 ----
    u64 a1[2][CH_];
    #pragma unroll
    for (int o = 0; o < CH_; o++) {
        const u64 b = sp[160 + o];
        a1[0][o] = b; a1[1][o] = b;
    }
    #pragma unroll
    for (int i = 0; i < CH_; i++) {
        const u64 x0 = h0[0][i];
        const u64 x1 = h0[1][i];
        #pragma unroll
        for (int o = 0; o < CH_; o++) {
            const u64 w = sp[80 + o * CH_ + i];
            a1[0][o] = ffma2(w, x0, a1[0][o]);
            a1[1][o] = ffma2(w, x1, a1[1][o]);
        }
    }
    #pragma unroll
    for (int o = 0; o < CH_; o++) {
        a1[0][o] = relu2(a1[0][o]);
        a1[1][o] = relu2(a1[1][o]);
    }

    // ---- layer 2: 8 -> 1 ----
    u64 r0 = sp[168];
    u64 r1 = r0;
    #pragma unroll
    for (int i = 0; i < CH_; i++) {
        const u64 w = sp[144 + i];
        r0 = ffma2(w, a1[0][i], r0);
        r1 = ffma2(w, a1[1][i], r1);
    }

    if (live) {
        float4 o4;
        unpack2(r0, o4.x, o4.y);
        unpack2(r1, o4.z, o4.w);
        *reinterpret_cast<float4*>(out + (size_t)inst * HW_ + p0) = o4;
    }
}

extern "C" void kernel_launch(void* const* d_in, const int* in_sizes, int n_in,
                              void* d_out, int out_size)
{
    const float* feats   = (const float*)d_in[0];
    const float* params  = (const float*)d_in[1];
    const float* locs    = (const float*)d_in[2];
    const float* soi     = (const float*)d_in[3];
    const int*   im_inds = (const int*)  d_in[4];
    const int*   fpn     = (const int*)  d_in[5];
    float*       out     = (float*)      d_out;

    dim3 grid(GRIDX, NINST_);
    dmh_kernel<<<grid, BLK>>>(feats, params, locs, soi, im_inds, fpn, out);
}

// round 3
// speedup vs baseline: 1.1740x; 1.0453x over previous
#include <cuda_runtime.h>

// DynamicMaskHead: per-instance 3-layer 1x1-conv MLP (10->8->8->1) over 27200 pixels.
// f32x2 FMA + transposed duplicated weights in shared (LDS.128 paired loads).

#define H_      136
#define W_      200
#define HW_     27200
#define CH_     8
#define INCH_   8
#define NINST_  128
#define NP_     169
#define STRIDE_ 8

#define BLK   256
#define NQ    (HW_ / 4)                 // 6800 float4 groups
#define GRIDX ((NQ + BLK - 1) / BLK)    // 27

typedef unsigned long long u64;

__device__ __forceinline__ u64 pack2(float lo, float hi) {
    u64 r; asm("mov.b64 %0, {%1, %2};" : "=l"(r) : "f"(lo), "f"(hi)); return r;
}
__device__ __forceinline__ void unpack2(u64 v, float& lo, float& hi) {
    asm("mov.b64 {%0, %1}, %2;" : "=f"(lo), "=f"(hi) : "l"(v));
}
__device__ __forceinline__ u64 ffma2(u64 a, u64 b, u64 c) {
    u64 d; asm("fma.rn.f32x2 %0, %1, %2, %3;" : "=l"(d) : "l"(a), "l"(b), "l"(c)); return d;
}
__device__ __forceinline__ u64 relu2(u64 v) {
    float lo, hi; unpack2(v, lo, hi);
    return pack2(fmaxf(lo, 0.0f), fmaxf(hi, 0.0f));
}

// param layout in gmem: w0 [0,80) (8x10) | w1 [80,144) (8x8) | w2 [144,152)
//                       b0 [152,160) | b1 [160,168) | b2 [168]
// shared layout (all u64 = weight duplicated into both f32x2 lanes):
//   sw0t[i*8+o] = w0[o][i]   (input-major -> outputs contiguous)
//   sw1t[i*8+o] = w1[o][i]
//   sw2[i], sb0[o], sb1[o], sb2[0]

struct __align__(16) SmemParams {
    u64 sw0t[80];
    u64 sw1t[64];
    u64 sw2[8];
    u64 sb0[8];
    u64 sb1[8];
    u64 sb2[2];      // [0] used, [1] pad for 16B
};

__global__ __launch_bounds__(BLK, 3)
void dmh_kernel(const float* __restrict__ feats,   // (2, 8, HW)
                const float* __restrict__ params,  // (128, 169)
                const float* __restrict__ locs,    // (128, 2)
                const float* __restrict__ soi,     // (5,)
                const int*   __restrict__ im_inds, // (128,)
                const int*   __restrict__ fpn,     // (128,)
                float*       __restrict__ out)     // (128, HW)
{
    __shared__ SmemParams S;
    __shared__ float smeta[3];
    __shared__ int   simg;

    const int inst = blockIdx.y;
    const int tid  = threadIdx.x;

    if (tid < NP_) {
        const float w = params[inst * NP_ + tid];
        const u64 d = pack2(w, w);
        if (tid < 80) {                       // w0: t = o*10 + i -> sw0t[i*8+o]
            const int o = tid / 10, i = tid - o * 10;
            S.sw0t[i * 8 + o] = d;
        } else if (tid < 144) {               // w1: k = o*8 + i -> sw1t[i*8+o]
            const int k = tid - 80;
            const int o = k >> 3, i = k & 7;
            S.sw1t[i * 8 + o] = d;
        } else if (tid < 152) {
            S.sw2[tid - 144] = d;
        } else if (tid < 160) {
            S.sb0[tid - 152] = d;
        } else if (tid < 168) {
            S.sb1[tid - 160] = d;
        } else {
            S.sb2[0] = d;
        }
    }
    if (tid == 0) {
        smeta[0] = locs[2 * inst + 0];
        smeta[1] = locs[2 * inst + 1];
        smeta[2] = 1.0f / soi[fpn[inst]];
        simg     = im_inds[inst];
    }
    __syncthreads();

    const float locx = smeta[0];
    const float locy = smeta[1];
    const float inv  = smeta[2];
    const float* __restrict__ fbase = feats + (size_t)simg * (INCH_ * HW_);

    const int q    = blockIdx.x * BLK + tid;
    const bool live = (q < NQ);
    const int qc   = live ? q : 0;
    const int p0   = qc * 4;                  // 4 consecutive pixels, same row (W%4==0)

    const int row  = qc / 50;
    const int col0 = (qc - row * 50) * 4;
    const float fy  = (float)(row * STRIDE_ + STRIDE_ / 2);
    const float fx0 = (float)(col0 * STRIDE_ + STRIDE_ / 2);

    // accumulators: 2 pixel-pair banks x 8 outputs
    u64 a0[2][CH_];
    {
        const ulonglong2* b = reinterpret_cast<const ulonglong2*>(S.sb0);
        #pragma unroll
        for (int oq = 0; oq < 4; oq++) {
            const ulonglong2 bb = b[oq];
            a0[0][2*oq]   = bb.x;  a0[1][2*oq]   = bb.x;
            a0[0][2*oq+1] = bb.y;  a0[1][2*oq+1] = bb.y;
        }
    }

    // helper macro: accumulate one input (x0 = pixels 0,1; x1 = pixels 2,3)
    #define ACCUM_INPUT(WROW, A)                                            \
        {                                                                   \
            const ulonglong2* wr = reinterpret_cast<const ulonglong2*>(WROW); \
            _Pragma("unroll")                                               \
            for (int oq = 0; oq < 4; oq++) {                                \
                const ulonglong2 w = wr[oq];                                \
                A[0][2*oq]   = ffma2(w.x, x0, A[0][2*oq]);                  \
                A[1][2*oq]   = ffma2(w.x, x1, A[1][2*oq]);                  \
                A[0][2*oq+1] = ffma2(w.y, x0, A[0][2*oq+1]);                \
                A[1][2*oq+1] = ffma2(w.y, x1, A[1][2*oq+1]);                \
            }                                                               \
        }

    {   // input 0: rel-x
        const u64 x0 = pack2((locx - fx0) * inv,          (locx - (fx0 +  8.0f)) * inv);
        const u64 x1 = pack2((locx - (fx0 + 16.0f)) * inv, (locx - (fx0 + 24.0f)) * inv);
        ACCUM_INPUT(&S.sw0t[0 * 8], a0)
    }
    {   // input 1: rel-y (uniform over the 4 pixels)
        const float ry = (locy - fy) * inv;
        const u64 x0 = pack2(ry, ry);
        const u64 x1 = x0;
        ACCUM_INPUT(&S.sw0t[1 * 8], a0)
    }
    #pragma unroll
    for (int c = 0; c < INCH_; c++) {   // inputs 2..9: feature channels
        const float4 f = *reinterpret_cast<const float4*>(fbase + (size_t)c * HW_ + p0);
        const u64 x0 = pack2(f.x, f.y);
        const u64 x1 = pack2(f.z, f.w);
        ACCUM_INPUT(&S.sw0t[(2 + c) * 8], a0)
    }

    // relu -> h0 (in place)
    #pragma unroll
    for (int o = 0; o < CH_; o++) {
        a0[0][o] = relu2(a0[0][o]);
        a0[1][o] = relu2(a0[1][o]);
    }

    // ---- layer 1: 8 -> 8 ----
    u64 a1[2][CH_];
    {
        const ulonglong2* b = reinterpret_cast<const ulonglong2*>(S.sb1);
        #pragma unroll
        for (int oq = 0; oq < 4; oq++) {
            const ulonglong2 bb = b[oq];
            a1[0][2*oq]   = bb.x;  a1[1][2*oq]   = bb.x;
            a1[0][2*oq+1] = bb.y;  a1[1][2*oq+1] = bb.y;
        }
    }
    #pragma unroll
    for (int i = 0; i < CH_; i++) {
        const u64 x0 = a0[0][i];
        const u64 x1 = a0[1][i];
        ACCUM_INPUT(&S.sw1t[i * 8], a1)
    }
    #pragma unroll
    for (int o = 0; o < CH_; o++) {
        a1[0][o] = relu2(a1[0][o]);
        a1[1][o] = relu2(a1[1][o]);
    }

    // ---- layer 2: 8 -> 1 ----
    u64 r0 = S.sb2[0];
    u64 r1 = r0;
    {
        const ulonglong2* wr = reinterpret_cast<const ulonglong2*>(S.sw2);
        #pragma unroll
        for (int iq = 0; iq < 4; iq++) {
            const ulonglong2 w = wr[iq];
            r0 = ffma2(w.x, a1[0][2*iq],   r0);
            r1 = ffma2(w.x, a1[1][2*iq],   r1);
            r0 = ffma2(w.y, a1[0][2*iq+1], r0);
            r1 = ffma2(w.y, a1[1][2*iq+1], r1);
        }
    }

    if (live) {
        float4 o4;
        unpack2(r0, o4.x, o4.y);
        unpack2(r1, o4.z, o4.w);
        *reinterpret_cast<float4*>(out + (size_t)inst * HW_ + p0) = o4;
    }
    #undef ACCUM_INPUT
}

extern "C" void kernel_launch(void* const* d_in, const int* in_sizes, int n_in,
                              void* d_out, int out_size)
{
    const float* feats   = (const float*)d_in[0];
    const float* params  = (const float*)d_in[1];
    const float* locs    = (const float*)d_in[2];
    const float* soi     = (const float*)d_in[3];
    const int*   im_inds = (const int*)  d_in[4];
    const int*   fpn     = (const int*)  d_in[5];
    float*       out     = (float*)      d_out;

    dim3 grid(GRIDX, NINST_);
    dmh_kernel<<<grid, BLK>>>(feats, params, locs, soi, im_inds, fpn, out);
}

// round 4
// speedup vs baseline: 1.1860x; 1.0102x over previous
#include <cuda_runtime.h>

// DynamicMaskHead: per-instance 3-layer 1x1-conv MLP (10->8->8->1) over 27200 pixels.
// f32x2 FMA + transposed duplicated weights in shared (LDS.128 paired loads).

#define H_      136
#define W_      200
#define HW_     27200
#define CH_     8
#define INCH_   8
#define NINST_  128
#define NP_     169
#define STRIDE_ 8

#define BLK   256
#define NQ    (HW_ / 4)                 // 6800 float4 groups
#define GRIDX ((NQ + BLK - 1) / BLK)    // 27

typedef unsigned long long u64;

__device__ __forceinline__ u64 pack2(float lo, float hi) {
    u64 r; asm("mov.b64 %0, {%1, %2};" : "=l"(r) : "f"(lo), "f"(hi)); return r;
}
__device__ __forceinline__ void unpack2(u64 v, float& lo, float& hi) {
    asm("mov.b64 {%0, %1}, %2;" : "=f"(lo), "=f"(hi) : "l"(v));
}
__device__ __forceinline__ u64 ffma2(u64 a, u64 b, u64 c) {
    u64 d; asm("fma.rn.f32x2 %0, %1, %2, %3;" : "=l"(d) : "l"(a), "l"(b), "l"(c)); return d;
}
__device__ __forceinline__ u64 relu2(u64 v) {
    float lo, hi; unpack2(v, lo, hi);
    return pack2(fmaxf(lo, 0.0f), fmaxf(hi, 0.0f));
}

// param layout in gmem: w0 [0,80) (8x10) | w1 [80,144) (8x8) | w2 [144,152)
//                       b0 [152,160) | b1 [160,168) | b2 [168]
// shared layout (all u64 = weight duplicated into both f32x2 lanes):
//   sw0t[i*8+o] = w0[o][i]   (input-major -> outputs contiguous)
//   sw1t[i*8+o] = w1[o][i]
//   sw2[i], sb0[o], sb1[o], sb2[0]

struct __align__(16) SmemParams {
    u64 sw0t[80];
    u64 sw1t[64];
    u64 sw2[8];
    u64 sb0[8];
    u64 sb1[8];
    u64 sb2[2];      // [0] used, [1] pad for 16B
};

__global__ __launch_bounds__(BLK, 3)
void dmh_kernel(const float* __restrict__ feats,   // (2, 8, HW)
                const float* __restrict__ params,  // (128, 169)
                const float* __restrict__ locs,    // (128, 2)
                const float* __restrict__ soi,     // (5,)
                const int*   __restrict__ im_inds, // (128,)
                const int*   __restrict__ fpn,     // (128,)
                float*       __restrict__ out)     // (128, HW)
{
    __shared__ SmemParams S;
    __shared__ float smeta[3];
    __shared__ int   simg;

    const int inst = blockIdx.y;
    const int tid  = threadIdx.x;

    if (tid < NP_) {
        const float w = params[inst * NP_ + tid];
        const u64 d = pack2(w, w);
        if (tid < 80) {                       // w0: t = o*10 + i -> sw0t[i*8+o]
            const int o = tid / 10, i = tid - o * 10;
            S.sw0t[i * 8 + o] = d;
        } else if (tid < 144) {               // w1: k = o*8 + i -> sw1t[i*8+o]
            const int k = tid - 80;
            const int o = k >> 3, i = k & 7;
            S.sw1t[i * 8 + o] = d;
        } else if (tid < 152) {
            S.sw2[tid - 144] = d;
        } else if (tid < 160) {
            S.sb0[tid - 152] = d;
        } else if (tid < 168) {
            S.sb1[tid - 160] = d;
        } else {
            S.sb2[0] = d;
        }
    }
    if (tid == 0) {
        smeta[0] = locs[2 * inst + 0];
        smeta[1] = locs[2 * inst + 1];
        smeta[2] = 1.0f / soi[fpn[inst]];
        simg     = im_inds[inst];
    }
    __syncthreads();

    const float locx = smeta[0];
    const float locy = smeta[1];
    const float inv  = smeta[2];
    const float* __restrict__ fbase = feats + (size_t)simg * (INCH_ * HW_);

    const int q    = blockIdx.x * BLK + tid;
    const bool live = (q < NQ);
    const int qc   = live ? q : 0;
    const int p0   = qc * 4;                  // 4 consecutive pixels, same row (W%4==0)

    const int row  = qc / 50;
    const int col0 = (qc - row * 50) * 4;
    const float fy  = (float)(row * STRIDE_ + STRIDE_ / 2);
    const float fx0 = (float)(col0 * STRIDE_ + STRIDE_ / 2);

    // accumulators: 2 pixel-pair banks x 8 outputs
    u64 a0[2][CH_];
    {
        const ulonglong2* b = reinterpret_cast<const ulonglong2*>(S.sb0);
        #pragma unroll
        for (int oq = 0; oq < 4; oq++) {
            const ulonglong2 bb = b[oq];
            a0[0][2*oq]   = bb.x;  a0[1][2*oq]   = bb.x;
            a0[0][2*oq+1] = bb.y;  a0[1][2*oq+1] = bb.y;
        }
    }

    // helper macro: accumulate one input (x0 = pixels 0,1; x1 = pixels 2,3)
    #define ACCUM_INPUT(WROW, A)                                            \
        {                                                                   \
            const ulonglong2* wr = reinterpret_cast<const ulonglong2*>(WROW); \
            _Pragma("unroll")                                               \
            for (int oq = 0; oq < 4; oq++) {                                \
                const ulonglong2 w = wr[oq];                                \
                A[0][2*oq]   = ffma2(w.x, x0, A[0][2*oq]);                  \
                A[1][2*oq]   = ffma2(w.x, x1, A[1][2*oq]);                  \
                A[0][2*oq+1] = ffma2(w.y, x0, A[0][2*oq+1]);                \
                A[1][2*oq+1] = ffma2(w.y, x1, A[1][2*oq+1]);                \
            }                                                               \
        }

    {   // input 0: rel-x
        const u64 x0 = pack2((locx - fx0) * inv,          (locx - (fx0 +  8.0f)) * inv);
        const u64 x1 = pack2((locx - (fx0 + 16.0f)) * inv, (locx - (fx0 + 24.0f)) * inv);
        ACCUM_INPUT(&S.sw0t[0 * 8], a0)
    }
    {   // input 1: rel-y (uniform over the 4 pixels)
        const float ry = (locy - fy) * inv;
        const u64 x0 = pack2(ry, ry);
        const u64 x1 = x0;
        ACCUM_INPUT(&S.sw0t[1 * 8], a0)
    }
    #pragma unroll
    for (int c = 0; c < INCH_; c++) {   // inputs 2..9: feature channels
        const float4 f = *reinterpret_cast<const float4*>(fbase + (size_t)c * HW_ + p0);
        const u64 x0 = pack2(f.x, f.y);
        const u64 x1 = pack2(f.z, f.w);
        ACCUM_INPUT(&S.sw0t[(2 + c) * 8], a0)
    }

    // relu -> h0 (in place)
    #pragma unroll
    for (int o = 0; o < CH_; o++) {
        a0[0][o] = relu2(a0[0][o]);
        a0[1][o] = relu2(a0[1][o]);
    }

    // ---- layer 1: 8 -> 8 ----
    u64 a1[2][CH_];
    {
        const ulonglong2* b = reinterpret_cast<const ulonglong2*>(S.sb1);
        #pragma unroll
        for (int oq = 0; oq < 4; oq++) {
            const ulonglong2 bb = b[oq];
            a1[0][2*oq]   = bb.x;  a1[1][2*oq]   = bb.x;
            a1[0][2*oq+1] = bb.y;  a1[1][2*oq+1] = bb.y;
        }
    }
    #pragma unroll
    for (int i = 0; i < CH_; i++) {
        const u64 x0 = a0[0][i];
        const u64 x1 = a0[1][i];
        ACCUM_INPUT(&S.sw1t[i * 8], a1)
    }
    #pragma unroll
    for (int o = 0; o < CH_; o++) {
        a1[0][o] = relu2(a1[0][o]);
        a1[1][o] = relu2(a1[1][o]);
    }

    // ---- layer 2: 8 -> 1 ----
    u64 r0 = S.sb2[0];
    u64 r1 = r0;
    {
        const ulonglong2* wr = reinterpret_cast<const ulonglong2*>(S.sw2);
        #pragma unroll
        for (int iq = 0; iq < 4; iq++) {
            const ulonglong2 w = wr[iq];
            r0 = ffma2(w.x, a1[0][2*iq],   r0);
            r1 = ffma2(w.x, a1[1][2*iq],   r1);
            r0 = ffma2(w.y, a1[0][2*iq+1], r0);
            r1 = ffma2(w.y, a1[1][2*iq+1], r1);
        }
    }

    if (live) {
        float4 o4;
        unpack2(r0, o4.x, o4.y);
        unpack2(r1, o4.z, o4.w);
        *reinterpret_cast<float4*>(out + (size_t)inst * HW_ + p0) = o4;
    }
    #undef ACCUM_INPUT
}

extern "C" void kernel_launch(void* const* d_in, const int* in_sizes, int n_in,
                              void* d_out, int out_size)
{
    const float* feats   = (const float*)d_in[0];
    const float* params  = (const float*)d_in[1];
    const float* locs    = (const float*)d_in[2];
    const float* soi     = (const float*)d_in[3];
    const int*   im_inds = (const int*)  d_in[4];
    const int*   fpn     = (const int*)  d_in[5];
    float*       out     = (float*)      d_out;

    dim3 grid(GRIDX, NINST_);
    dmh_kernel<<<grid, BLK>>>(feats, params, locs, soi, im_inds, fpn, out);
}